// round 1
// baseline (speedup 1.0000x reference)
#include <cuda_runtime.h>
#include <cstdint>

#define B_ROWS   16384
#define D_DIM    256
#define T_TRIP   262144
#define MARGIN   0.1f
#define EPS_F    1e-6f

#define WARPS_PER_BLOCK 8
#define TRIPS_PER_WARP  8
// 4096 blocks * 8 warps * 8 triplets = 262144 == T_TRIP exactly
#define TRIP_BLOCKS (T_TRIP / (WARPS_PER_BLOCK * TRIPS_PER_WARP))

// Scratch: per-row reciprocal norms (device global, no allocation).
__device__ float g_inv_norm[B_ROWS];

// Kernel 1: one warp per row -> inv_norm[b] = 1 / max(||pred[b]||, eps).
// Also zeroes the output accumulator (d_out is poisoned to 0xAA).
__global__ void __launch_bounds__(256)
tl_norm_kernel(const float* __restrict__ pred, float* __restrict__ out)
{
    if (blockIdx.x == 0 && threadIdx.x == 0) out[0] = 0.0f;

    const int warp = (blockIdx.x * blockDim.x + threadIdx.x) >> 5;
    const int lane = threadIdx.x & 31;
    if (warp >= B_ROWS) return;

    const float4* row = reinterpret_cast<const float4*>(pred + (size_t)warp * D_DIM);
    float s = 0.0f;
    float4 v0 = row[lane];
    float4 v1 = row[lane + 32];
    s += v0.x*v0.x + v0.y*v0.y + v0.z*v0.z + v0.w*v0.w;
    s += v1.x*v1.x + v1.y*v1.y + v1.z*v1.z + v1.w*v1.w;

    #pragma unroll
    for (int o = 16; o > 0; o >>= 1)
        s += __shfl_xor_sync(0xFFFFFFFFu, s, o);

    if (lane == 0) {
        float n = sqrtf(s);
        g_inv_norm[warp] = 1.0f / fmaxf(n, EPS_F);
    }
}

// Kernel 2: one warp per triplet (x TRIPS_PER_WARP), gather a/p/n rows
// (L2-resident), compute cos(a,p)-cos(a,n)+M, relu, block-reduce, one atomic.
__global__ void __launch_bounds__(WARPS_PER_BLOCK * 32)
tl_triplet_kernel(const float* __restrict__ pred,
                  const long long* __restrict__ anchor_idx,
                  const long long* __restrict__ pos_idx,
                  const long long* __restrict__ neg_idx,
                  float* __restrict__ out)
{
    const int lane = threadIdx.x & 31;
    const int wid  = threadIdx.x >> 5;
    const int gwarp = blockIdx.x * WARPS_PER_BLOCK + wid;
    const int total_warps = TRIP_BLOCKS * WARPS_PER_BLOCK;

    float acc = 0.0f;

    #pragma unroll
    for (int i = 0; i < TRIPS_PER_WARP; i++) {
        const int t = gwarp + i * total_warps;

        // Uniform loads (all lanes same address -> broadcast).
        const int a = (int)anchor_idx[t];
        const int p = (int)pos_idx[t];
        const int n = (int)neg_idx[t];

        const float4* ra = reinterpret_cast<const float4*>(pred + (size_t)a * D_DIM) + lane;
        const float4* rp = reinterpret_cast<const float4*>(pred + (size_t)p * D_DIM) + lane;
        const float4* rn = reinterpret_cast<const float4*>(pred + (size_t)n * D_DIM) + lane;

        // 6 independent LDG.128 per lane -> high MLP to hide L2 latency.
        float4 a0 = ra[0],  a1 = ra[32];
        float4 p0 = rp[0],  p1 = rp[32];
        float4 n0 = rn[0],  n1 = rn[32];

        float dap = a0.x*p0.x + a0.y*p0.y + a0.z*p0.z + a0.w*p0.w
                  + a1.x*p1.x + a1.y*p1.y + a1.z*p1.z + a1.w*p1.w;
        float dan = a0.x*n0.x + a0.y*n0.y + a0.z*n0.z + a0.w*n0.w
                  + a1.x*n1.x + a1.y*n1.y + a1.z*n1.z + a1.w*n1.w;

        #pragma unroll
        for (int o = 16; o > 0; o >>= 1) {
            dap += __shfl_xor_sync(0xFFFFFFFFu, dap, o);
            dan += __shfl_xor_sync(0xFFFFFFFFu, dan, o);
        }

        if (lane == 0) {
            const float ina = g_inv_norm[a];
            const float cv = dap * ina * g_inv_norm[p]
                           - dan * ina * g_inv_norm[n] + MARGIN;
            acc += fmaxf(cv, 0.0f);
        }
    }

    __shared__ float sacc[WARPS_PER_BLOCK];
    if (lane == 0) sacc[wid] = acc;
    __syncthreads();

    if (threadIdx.x == 0) {
        float s = 0.0f;
        #pragma unroll
        for (int i = 0; i < WARPS_PER_BLOCK; i++) s += sacc[i];
        atomicAdd(out, s * (1.0f / (float)T_TRIP));
    }
}

extern "C" void kernel_launch(void* const* d_in, const int* in_sizes, int n_in,
                              void* d_out, int out_size)
{
    const float*     pred = (const float*)d_in[0];
    const long long* ai   = (const long long*)d_in[1];
    const long long* pi   = (const long long*)d_in[2];
    const long long* ni   = (const long long*)d_in[3];
    float* out = (float*)d_out;

    // 16384 rows, one warp each: 2048 blocks x 256 threads.
    tl_norm_kernel<<<B_ROWS / 8, 256>>>(pred, out);
    tl_triplet_kernel<<<TRIP_BLOCKS, WARPS_PER_BLOCK * 32>>>(pred, ai, pi, ni, out);
}

// round 3
// speedup vs baseline: 1.6451x; 1.6451x over previous
#include <cuda_runtime.h>
#include <cuda_fp16.h>
#include <cstdint>

#define B_ROWS   16384
#define D_DIM    256
#define T_TRIP   262144
#define MARGIN   0.1f
#define EPS_F    1e-6f

#define WARPS_PER_BLOCK 8
#define TRIPS_PER_WARP  8
// 4096 blocks * 8 warps * 8 triplets = 262144 == T_TRIP
#define TRIP_BLOCKS (T_TRIP / (WARPS_PER_BLOCK * TRIPS_PER_WARP))

// Normalized fp16 copy of pred: row r = pred[r] / max(||pred[r]||, eps).
// 16384 * 256 * 2B = 8 MB device-global scratch (no allocation).
__device__ __half g_pred_h[B_ROWS * D_DIM];

// Kernel 1: one warp per row. Compute inv-norm, write normalized fp16 row.
// Also zeroes the output accumulator (d_out is poisoned).
__global__ void __launch_bounds__(256)
tl_normalize_kernel(const float* __restrict__ pred, float* __restrict__ out)
{
    if (blockIdx.x == 0 && threadIdx.x == 0) out[0] = 0.0f;

    const int row  = (blockIdx.x * blockDim.x + threadIdx.x) >> 5;
    const int lane = threadIdx.x & 31;
    if (row >= B_ROWS) return;

    // Lane handles 8 contiguous floats: indices [lane*8, lane*8+8).
    const float4* src = reinterpret_cast<const float4*>(pred + (size_t)row * D_DIM);
    float4 v0 = src[2 * lane];
    float4 v1 = src[2 * lane + 1];

    float s = v0.x*v0.x + v0.y*v0.y + v0.z*v0.z + v0.w*v0.w
            + v1.x*v1.x + v1.y*v1.y + v1.z*v1.z + v1.w*v1.w;
    #pragma unroll
    for (int o = 16; o > 0; o >>= 1)
        s += __shfl_xor_sync(0xFFFFFFFFu, s, o);   // butterfly: all lanes get sum

    const float inv = 1.0f / fmaxf(sqrtf(s), EPS_F);

    __half2 h0 = __floats2half2_rn(v0.x * inv, v0.y * inv);
    __half2 h1 = __floats2half2_rn(v0.z * inv, v0.w * inv);
    __half2 h2 = __floats2half2_rn(v1.x * inv, v1.y * inv);
    __half2 h3 = __floats2half2_rn(v1.z * inv, v1.w * inv);

    uint4 u;
    u.x = *reinterpret_cast<unsigned*>(&h0);
    u.y = *reinterpret_cast<unsigned*>(&h1);
    u.z = *reinterpret_cast<unsigned*>(&h2);
    u.w = *reinterpret_cast<unsigned*>(&h3);
    reinterpret_cast<uint4*>(g_pred_h + (size_t)row * D_DIM)[lane] = u;
}

// Accumulate a * (p - n) into s for one half2 group of each vector.
__device__ __forceinline__ void acc_diff(float& s, unsigned au, unsigned pu, unsigned nu)
{
    float2 fa = __half22float2(*reinterpret_cast<__half2*>(&au));
    float2 fp = __half22float2(*reinterpret_cast<__half2*>(&pu));
    float2 fn = __half22float2(*reinterpret_cast<__half2*>(&nu));
    s = fmaf(fa.x, fp.x - fn.x, s);
    s = fmaf(fa.y, fp.y - fn.y, s);
}

// Kernel 2: one warp per triplet (x TRIPS_PER_WARP).
// Gathers are LDG.64 (2 cache lines per warp-instruction) to stay on the
// ~1 cyc/wavefront cross-LDG L1tex rate instead of 2.07 cyc/wf replays.
__global__ void __launch_bounds__(WARPS_PER_BLOCK * 32)
tl_triplet_kernel(const long long* __restrict__ anchor_idx,
                  const long long* __restrict__ pos_idx,
                  const long long* __restrict__ neg_idx,
                  float* __restrict__ out)
{
    const int lane = threadIdx.x & 31;
    const int wid  = threadIdx.x >> 5;
    const int gwarp = blockIdx.x * WARPS_PER_BLOCK + wid;
    const int total_warps = TRIP_BLOCKS * WARPS_PER_BLOCK;

    float acc = 0.0f;

    #pragma unroll
    for (int i = 0; i < TRIPS_PER_WARP; i++) {
        const int t = gwarp + i * total_warps;

        const int a = (int)__ldg(&anchor_idx[t]);   // uniform -> broadcast
        const int p = (int)__ldg(&pos_idx[t]);
        const int n = (int)__ldg(&neg_idx[t]);

        // Row = 512 B of fp16. Lane reads 8 B from each 256 B half-row.
        const uint2* ra = reinterpret_cast<const uint2*>(g_pred_h + (size_t)a * D_DIM) + lane;
        const uint2* rp = reinterpret_cast<const uint2*>(g_pred_h + (size_t)p * D_DIM) + lane;
        const uint2* rn = reinterpret_cast<const uint2*>(g_pred_h + (size_t)n * D_DIM) + lane;

        uint2 a0 = ra[0], a1 = ra[32];
        uint2 p0 = rp[0], p1 = rp[32];
        uint2 n0 = rn[0], n1 = rn[32];

        // s = dot(a,p) - dot(a,n) per lane (vectors are pre-normalized).
        float s = 0.0f;
        acc_diff(s, a0.x, p0.x, n0.x);
        acc_diff(s, a0.y, p0.y, n0.y);
        acc_diff(s, a1.x, p1.x, n1.x);
        acc_diff(s, a1.y, p1.y, n1.y);

        #pragma unroll
        for (int o = 16; o > 0; o >>= 1)
            s += __shfl_xor_sync(0xFFFFFFFFu, s, o);

        if (lane == 0)
            acc += fmaxf(s + MARGIN, 0.0f);
    }

    __shared__ float sacc[WARPS_PER_BLOCK];
    if (lane == 0) sacc[wid] = acc;
    __syncthreads();

    if (threadIdx.x == 0) {
        float sum = 0.0f;
        #pragma unroll
        for (int i = 0; i < WARPS_PER_BLOCK; i++) sum += sacc[i];
        atomicAdd(out, sum * (1.0f / (float)T_TRIP));
    }
}

extern "C" void kernel_launch(void* const* d_in, const int* in_sizes, int n_in,
                              void* d_out, int out_size)
{
    const float*     pred = (const float*)d_in[0];
    const long long* ai   = (const long long*)d_in[1];
    const long long* pi   = (const long long*)d_in[2];
    const long long* ni   = (const long long*)d_in[3];
    float* out = (float*)d_out;

    tl_normalize_kernel<<<B_ROWS / 8, 256>>>(pred, out);
    tl_triplet_kernel<<<TRIP_BLOCKS, WARPS_PER_BLOCK * 32>>>(ai, pi, ni, out);
}

// round 8
// speedup vs baseline: 1.8915x; 1.1498x over previous
#include <cuda_runtime.h>
#include <cuda_fp16.h>
#include <cstdint>

#define B_ROWS   16384
#define D_DIM    256
#define T_TRIP   262144
#define MARGIN   0.1f
#define EPS_F    1e-6f
#define ROW_MASK (B_ROWS - 1)

#define WARPS_PER_BLOCK 8
#define ITERS 4
// each warp-iteration handles 4 triplets (8 lanes per triplet)
// 2048 blocks * 8 warps * 4 iters * 4 triplets = 262144 == T_TRIP
#define TRIP_BLOCKS (T_TRIP / (WARPS_PER_BLOCK * ITERS * 4))

// Normalized fp16 copy of pred as uint4 (16B-aligned by type).
// Row = 256 halves = 32 uint4. 8 MB device-global scratch.
#define ROW_U4 (D_DIM / 8)
__device__ uint4 g_pred_q[B_ROWS * ROW_U4];

// Kernel 1: one warp per row -> normalized fp16 row. Zeroes d_out.
__global__ void __launch_bounds__(256)
tl_normalize_kernel(const float* __restrict__ pred, float* __restrict__ out)
{
    if (blockIdx.x == 0 && threadIdx.x == 0) out[0] = 0.0f;

    const int row  = (blockIdx.x * blockDim.x + threadIdx.x) >> 5;
    const int lane = threadIdx.x & 31;
    if (row >= B_ROWS) return;

    const float4* src = reinterpret_cast<const float4*>(pred + (size_t)row * D_DIM);
    float4 v0 = src[2 * lane];
    float4 v1 = src[2 * lane + 1];

    float s = v0.x*v0.x + v0.y*v0.y + v0.z*v0.z + v0.w*v0.w
            + v1.x*v1.x + v1.y*v1.y + v1.z*v1.z + v1.w*v1.w;
    #pragma unroll
    for (int o = 16; o > 0; o >>= 1)
        s += __shfl_xor_sync(0xFFFFFFFFu, s, o);   // all lanes get the sum

    const float inv = 1.0f / fmaxf(sqrtf(s), EPS_F);

    __half2 h0 = __floats2half2_rn(v0.x * inv, v0.y * inv);
    __half2 h1 = __floats2half2_rn(v0.z * inv, v0.w * inv);
    __half2 h2 = __floats2half2_rn(v1.x * inv, v1.y * inv);
    __half2 h3 = __floats2half2_rn(v1.z * inv, v1.w * inv);

    uint4 u;
    u.x = *reinterpret_cast<unsigned*>(&h0);
    u.y = *reinterpret_cast<unsigned*>(&h1);
    u.z = *reinterpret_cast<unsigned*>(&h2);
    u.w = *reinterpret_cast<unsigned*>(&h3);
    g_pred_q[row * ROW_U4 + lane] = u;
}

__device__ __forceinline__ __half2 u2h(unsigned u)
{
    __half2 h;
    *reinterpret_cast<unsigned*>(&h) = u;
    return h;
}

// dot(a, p - n) for 8 fp16 elems: fp16 products (one pairwise HADD2 level),
// fp32 final sums.
__device__ __forceinline__ float dot_diff8(uint4 a, uint4 p, uint4 n)
{
    __half2 m0 = __hmul2(u2h(a.x), __hsub2(u2h(p.x), u2h(n.x)));
    __half2 m1 = __hmul2(u2h(a.y), __hsub2(u2h(p.y), u2h(n.y)));
    __half2 m2 = __hmul2(u2h(a.z), __hsub2(u2h(p.z), u2h(n.z)));
    __half2 m3 = __hmul2(u2h(a.w), __hsub2(u2h(p.w), u2h(n.w)));
    float2 f01 = __half22float2(__hadd2(m0, m1));
    float2 f23 = __half22float2(__hadd2(m2, m3));
    return (f01.x + f01.y) + (f23.x + f23.y);
}

// Kernel 2: 8 lanes per triplet, 4 triplets per warp per iteration.
// Row indices masked to [0, B_ROWS) -> every address bounded by constants.
__global__ void __launch_bounds__(WARPS_PER_BLOCK * 32)
tl_triplet_kernel(const long long* __restrict__ anchor_idx,
                  const long long* __restrict__ pos_idx,
                  const long long* __restrict__ neg_idx,
                  float* __restrict__ out)
{
    const int lane = threadIdx.x & 31;
    const int wid  = threadIdx.x >> 5;
    const int seg  = lane >> 3;   // 0..3 : which triplet in this warp
    const int sub  = lane & 7;    // 0..7 : position within triplet
    const int gwarp = blockIdx.x * WARPS_PER_BLOCK + wid;

    float acc = 0.0f;

    #pragma unroll
    for (int it = 0; it < ITERS; it++) {
        const int t = (gwarp * ITERS + it) * 4 + seg;   // < T_TRIP by construction

        const int a = ((int)anchor_idx[t]) & ROW_MASK;  // identity for valid input
        const int p = ((int)pos_idx[t])    & ROW_MASK;
        const int n = ((int)neg_idx[t])    & ROW_MASK;

        // Row = 32 uint4. Lane covers uint4 indices {sub, sub+8, sub+16, sub+24}.
        const uint4* ra = g_pred_q + a * ROW_U4 + sub;
        const uint4* rp = g_pred_q + p * ROW_U4 + sub;
        const uint4* rn = g_pred_q + n * ROW_U4 + sub;

        uint4 av[4], pv[4], nv[4];
        #pragma unroll
        for (int c = 0; c < 4; c++) {
            av[c] = ra[c * 8];
            pv[c] = rp[c * 8];
            nv[c] = rn[c * 8];
        }

        float s = 0.0f;
        #pragma unroll
        for (int c = 0; c < 4; c++)
            s += dot_diff8(av[c], pv[c], nv[c]);

        // Segmented butterfly within each 8-lane group.
        #pragma unroll
        for (int o = 1; o < 8; o <<= 1)
            s += __shfl_xor_sync(0xFFFFFFFFu, s, o);

        // Each lane of the segment now holds the segment sum.
        acc += fmaxf(s + MARGIN, 0.0f);
    }

    // Combine the 4 segments: lanes within a segment agree, so xor-8 + xor-16
    // leaves every lane with seg0+seg1+seg2+seg3 (each segment counted ONCE).
    acc += __shfl_xor_sync(0xFFFFFFFFu, acc, 8);
    acc += __shfl_xor_sync(0xFFFFFFFFu, acc, 16);

    __shared__ float sacc[WARPS_PER_BLOCK];
    if (lane == 0) sacc[wid] = acc;
    __syncthreads();

    if (threadIdx.x == 0) {
        float sum = 0.0f;
        #pragma unroll
        for (int i = 0; i < WARPS_PER_BLOCK; i++) sum += sacc[i];
        // Each triplet contributes exactly once per warp -> scale by 1/T.
        atomicAdd(out, sum * (1.0f / (float)T_TRIP));
    }
}

extern "C" void kernel_launch(void* const* d_in, const int* in_sizes, int n_in,
                              void* d_out, int out_size)
{
    const float*     pred = (const float*)d_in[0];
    const long long* ai   = (const long long*)d_in[1];
    const long long* pi   = (const long long*)d_in[2];
    const long long* ni   = (const long long*)d_in[3];
    float* out = (float*)d_out;

    tl_normalize_kernel<<<B_ROWS / 8, 256>>>(pred, out);
    tl_triplet_kernel<<<TRIP_BLOCKS, WARPS_PER_BLOCK * 32>>>(ai, pi, ni, out);
}